// round 4
// baseline (speedup 1.0000x reference)
#include <cuda_runtime.h>
#include <cstdint>

#define HH 512
#define WW 512
#define HWSZ (HH*WW)
#define BB 16
#define NJOB 48
#define NWORDS 8192   /* 512 rows * 16 words */
#define WPR 16
#define NMEANBLK 1024

__device__ double g_mean_partial[NMEANBLK];
__device__ float  g_job_out[NJOB * 6];

__device__ __forceinline__ uint32_t rotl32(uint32_t x, int r) {
    return (x << r) | (x >> (32 - r));
}

// JAX threefry2x32 (20 rounds, key schedule per jax/_src/prng.py)
__device__ __forceinline__ void threefry(uint32_t k0, uint32_t k1,
                                         uint32_t x0, uint32_t x1,
                                         uint32_t &o0, uint32_t &o1) {
    uint32_t k2 = k0 ^ k1 ^ 0x1BD11BDAu;
    uint32_t a = x0 + k0, b = x1 + k1;
#define RND(r) { a += b; b = rotl32(b, r); b ^= a; }
    RND(13) RND(15) RND(26) RND(6)  a += k1; b += k2 + 1u;
    RND(17) RND(29) RND(16) RND(24) a += k2; b += k0 + 2u;
    RND(13) RND(15) RND(26) RND(6)  a += k0; b += k1 + 3u;
    RND(17) RND(29) RND(16) RND(24) a += k1; b += k2 + 4u;
    RND(13) RND(15) RND(26) RND(6)  a += k2; b += k0 + 5u;
#undef RND
    o0 = a; o1 = b;
}

// ---------------- Kernel A: mean |pred - target| partials ----------------
__global__ void k_meanabs(const float* __restrict__ p,
                          const float* __restrict__ t, int n) {
    __shared__ double sh[256];
    double s = 0.0;
    int stride = gridDim.x * blockDim.x;
    for (int i = blockIdx.x * blockDim.x + threadIdx.x; i < n; i += stride)
        s += (double)fabsf(p[i] - t[i]);
    sh[threadIdx.x] = s;
    __syncthreads();
    for (int o = 128; o > 0; o >>= 1) {
        if (threadIdx.x < o) sh[threadIdx.x] += sh[threadIdx.x + o];
        __syncthreads();
    }
    if (threadIdx.x == 0) g_mean_partial[blockIdx.x] = sh[0];
}

// deterministic block reduce of a double (512 threads / 16 warps)
__device__ double blockReduceD(double v, double* red) {
    int lane = threadIdx.x & 31, warp = threadIdx.x >> 5;
    for (int o = 16; o; o >>= 1) v += __shfl_down_sync(0xffffffffu, v, o);
    __syncthreads();                 // protect red from previous use
    if (lane == 0) red[warp] = v;
    __syncthreads();
    if (warp == 0) {
        double r = (lane < 16) ? red[lane] : 0.0;
        for (int o = 8; o; o >>= 1) r += __shfl_down_sync(0xffffffffu, r, o);
        if (lane == 0) red[0] = r;
    }
    __syncthreads();
    return red[0];
}

// ---------------- Kernel B: one block per (batch, label) job ----------------
__global__ void __launch_bounds__(512)
k_region(const float* __restrict__ pred, const int* __restrict__ lab14,
         const float* __restrict__ img1, const float* __restrict__ img2) {
    extern __shared__ uint32_t sm[];
    uint32_t* M  = sm;               // region mask
    uint32_t* Tb = sm + NWORDS;      // temp (horizontal erosion)
    uint32_t* E1 = sm + 2 * NWORDS;  // erode once
    uint32_t* E2 = sm + 3 * NWORDS;  // erode twice

    __shared__ int   rowpref[HH];
    __shared__ int   samp[200];
    __shared__ float pairbuf[200];
    __shared__ double red[16];
    __shared__ int   icnt[4];

    const int tid = threadIdx.x, lane = tid & 31, warp = tid >> 5;
    const int job = blockIdx.x;
    const int b = job / 3, li = job - 3 * b;
    const int   labels[3] = {5, 8, 13};
    const float tgts[3]   = {0.077f, 0.227f, 0.348f};
    const int   label = labels[li];
    const float tgtcv = tgts[li];

    const int*   lab = lab14 + (size_t)b * HWSZ;
    const float* P   = pred  + (size_t)b * HWSZ;

    if (tid < 4) icnt[tid] = 0;

    // ---- build region bitmask via ballot (coalesced) ----
#pragma unroll 4
    for (int w = warp; w < NWORDS; w += 16) {
        int base = w << 5;
        uint32_t bit = (lab[base + lane] == label) ? 1u : 0u;
        uint32_t word = __ballot_sync(0xffffffffu, bit);
        if (lane == 0) M[w] = word;
    }
    __syncthreads();

    // ---- erosion 1: horizontal (edge fill = 1, matching SAME+inf pad) ----
    for (int i = tid; i < NWORDS; i += 512) {
        int wc = i & 15;
        uint32_t m = M[i];
        uint32_t l = (m << 1) | (wc ? (M[i - 1] >> 31) : 1u);
        uint32_t r = (m >> 1) | ((wc < 15) ? (M[i + 1] << 31) : 0x80000000u);
        Tb[i] = m & l & r;
    }
    __syncthreads();
    // vertical
    for (int i = tid; i < NWORDS; i += 512) {
        uint32_t v = Tb[i];
        if (i >= WPR)          v &= Tb[i - WPR];
        if (i < NWORDS - WPR)  v &= Tb[i + WPR];
        E1[i] = v;
    }
    __syncthreads();
    // ---- erosion 2 from E1 ----
    for (int i = tid; i < NWORDS; i += 512) {
        int wc = i & 15;
        uint32_t m = E1[i];
        uint32_t l = (m << 1) | (wc ? (E1[i - 1] >> 31) : 1u);
        uint32_t r = (m >> 1) | ((wc < 15) ? (E1[i + 1] << 31) : 0x80000000u);
        Tb[i] = m & l & r;
    }
    __syncthreads();
    for (int i = tid; i < NWORDS; i += 512) {
        uint32_t v = Tb[i];
        if (i >= WPR)          v &= Tb[i - WPR];
        if (i < NWORDS - WPR)  v &= Tb[i + WPR];
        E2[i] = v;
    }
    __syncthreads();

    // ---- popcounts ----
    {
        int c0 = 0, c1 = 0, c2 = 0;
        for (int i = tid; i < NWORDS; i += 512) {
            c0 += __popc(M[i]); c1 += __popc(E1[i]); c2 += __popc(E2[i]);
        }
        for (int o = 16; o; o >>= 1) {
            c0 += __shfl_down_sync(0xffffffffu, c0, o);
            c1 += __shfl_down_sync(0xffffffffu, c1, o);
            c2 += __shfl_down_sync(0xffffffffu, c2, o);
        }
        if (lane == 0) {
            atomicAdd(&icnt[0], c0);
            atomicAdd(&icnt[1], c1);
            atomicAdd(&icnt[2], c2);
        }
    }
    __syncthreads();
    const int n_reg = icnt[0], nE1 = icnt[1], nE2 = icnt[2];
    const uint32_t* C1 = (nE1 < 2) ? M  : E1;
    const int       n1 = (nE1 < 2) ? n_reg : nE1;
    const uint32_t* C2 = (nE2 < 3) ? C1 : E2;
    const int       n2 = (nE2 < 3) ? n1 : nE2;

    // ---- stats + smoothness pass over core2 ----
    double s = 0.0, s2 = 0.0, sdx = 0.0, sdy = 0.0;
    int cx = 0, cy = 0;
#pragma unroll 2
    for (int w = warp; w < NWORDS; w += 16) {
        uint32_t word = C2[w];
        if (!word) continue;
        bool in = (word >> lane) & 1u;
        if (!in) continue;
        int wc = w & 15;
        int idx = (w << 5) + lane;
        float v = P[idx];
        s += (double)v; s2 += (double)v * (double)v;
        uint32_t right;
        if (lane < 31) right = (word >> (lane + 1)) & 1u;
        else           right = (wc < 15) ? (C2[w + 1] & 1u) : 0u;
        if (right) { float vr = P[idx + 1];  sdx += (double)fabsf(vr - v); cx++; }
        uint32_t down = (w < NWORDS - WPR) ? ((C2[w + WPR] >> lane) & 1u) : 0u;
        if (down)  { float vd = P[idx + WW]; sdy += (double)fabsf(vd - v); cy++; }
    }
    double S  = blockReduceD(s,  red);
    double S2 = blockReduceD(s2, red);
    double SDX = blockReduceD(sdx, red);
    double SDY = blockReduceD(sdy, red);
    double CX = blockReduceD((double)cx, red);
    double CY = blockReduceD((double)cy, red);

    // ---- core1 row prefix counts (for pair sampling) ----
    if (tid < HH) {
        int base = tid * WPR, c = 0;
#pragma unroll
        for (int k = 0; k < WPR; k++) c += __popc(C1[base + k]);
        rowpref[tid] = c;
    }
    __syncthreads();
    if (tid == 0) {
        int acc = 0;
        for (int r = 0; r < HH; r++) { acc += rowpref[r]; rowpref[r] = acc; }
    }
    __syncthreads();

    // ---- rank-pair sampling (JAX threefry path) ----
    if (n1 >= 1 && tid < 200) {
        // key_job from split(key(42), 48)
        uint32_t o0a, o1a, o0b, o1b, ka, kb;
        int i0, i1; bool first;
        if (job < 24) { i0 = 2 * job;      i1 = 2 * job + 1;  first = true;  }
        else          { i0 = 2 * job - 48; i1 = 2 * job - 47; first = false; }
        threefry(0u, 42u, (uint32_t)i0, (uint32_t)(48 + i0), o0a, o1a);
        threefry(0u, 42u, (uint32_t)i1, (uint32_t)(48 + i1), o0b, o1b);
        ka = first ? o0a : o1a;  kb = first ? o0b : o1b;
        // split(key_job) -> k1, k2
        uint32_t p00, p01, p10, p11;
        threefry(ka, kb, 0u, 2u, p00, p01);
        threefry(ka, kb, 1u, 3u, p10, p11);
        uint32_t qk0, qk1;
        if (tid < 100) { qk0 = p00; qk1 = p10; }   // k1 -> ii
        else           { qk0 = p01; qk1 = p11; }   // k2 -> jj
        int q = (tid < 100) ? tid : tid - 100;
        // uniform bits: counts iota(100) split [0:50),[50:100)
        uint32_t b0, b1, bits;
        if (q < 50) { threefry(qk0, qk1, (uint32_t)q,        (uint32_t)(50 + q), b0, b1); bits = b0; }
        else        { threefry(qk0, qk1, (uint32_t)(q - 50), (uint32_t)q,        b0, b1); bits = b1; }
        float u = __uint_as_float((bits >> 9) | 0x3f800000u) - 1.0f;
        float r = 1.0f - u;
        int m = (int)ceilf((float)n1 * r);
        m = min(max(m, 1), n1);
        // binary search row
        int lo = 0, hi = HH - 1;
        while (lo < hi) { int mid = (lo + hi) >> 1; if (rowpref[mid] >= m) hi = mid; else lo = mid + 1; }
        int row = lo;
        int rem = m - (row ? rowpref[row - 1] : 0);
        int base = row * WPR, col = 0;
        for (int kw = 0; kw < WPR; kw++) {
            uint32_t wv = C1[base + kw];
            int pc = __popc(wv);
            if (rem <= pc) {
                for (int z = 1; z < rem; z++) wv &= wv - 1;
                col = (kw << 5) + (__ffs(wv) - 1);
                break;
            }
            rem -= pc;
        }
        samp[tid] = row * WW + col;
    }
    __syncthreads();

    if (n1 >= 1) {
        if (tid < 100) {
            const float* T1 = img1 + (size_t)b * HWSZ;
            const float* T2 = img2 + (size_t)b * HWSZ;
            int ia = samp[tid], jb = samp[100 + tid];
            float xi = 0.5f * (1.0f - T1[ia]) + 0.5f * T2[ia];
            float xj = 0.5f * (1.0f - T1[jb]) + 0.5f * T2[jb];
            float d = xi - xj;
            float sg = (d > 0.0f) ? 1.0f : ((d < 0.0f) ? -1.0f : 0.0f);
            float pv = (ia != jb && sg != 0.0f) ? 1.0f : 0.0f;
            float hinge = fmaxf(0.0f, -(P[ia] - P[jb]) * sg);
            pairbuf[tid] = hinge * pv;
            pairbuf[100 + tid] = pv;
        }
        __syncthreads();
    }

    // ---- job outputs ----
    if (tid == 0) {
        double n2s = (n2 > 1) ? (double)n2 : 1.0;
        double mu = S / n2s;
        double var = S2 / n2s - mu * mu;
        if (var < 0.0) var = 0.0;
        float cv = (float)(sqrt(var) / (fabs(mu) + 1e-6));
        float sv = fabsf(cv - tgtcv);
        float svd = (n_reg >= 3 && n2 >= 3) ? 1.0f : 0.0f;

        double mean_x = SDX / ((CX > 1.0) ? CX : 1.0);
        double mean_y = SDY / ((CY > 1.0) ? CY : 1.0);
        float hx = (CX > 0.0) ? 1.0f : 0.0f;
        float hy = (CY > 0.0) ? 1.0f : 0.0f;
        float npres = hx + hy;
        float mval = (float)((mean_x * hx + mean_y * hy) / ((npres > 1.0f) ? npres : 1.0f));
        float mvd = (n_reg >= 3 && n2 >= 3 && npres > 0.0f) ? 1.0f : 0.0f;

        float hs = 0.0f, npv = 0.0f;
        if (n1 >= 1) {
            for (int i = 0; i < 100; i++) { hs += pairbuf[i]; npv += pairbuf[100 + i]; }
        }
        float rv = hs / fmaxf(npv, 1.0f);
        float rvd = (n_reg >= 2 && n1 >= 2 && npv > 0.0f) ? 1.0f : 0.0f;

        float* o = g_job_out + job * 6;
        o[0] = sv;   o[1] = svd;
        o[2] = rv;   o[3] = rvd;
        o[4] = mval; o[5] = mvd;
    }
}

// ---------------- Kernel C: finalize ----------------
__global__ void k_final(float* __restrict__ out) {
    __shared__ double sh[256];
    int tid = threadIdx.x;
    double s = 0.0;
    for (int i = tid; i < NMEANBLK; i += 256) s += g_mean_partial[i];
    sh[tid] = s;
    __syncthreads();
    for (int o = 128; o > 0; o >>= 1) {
        if (tid < o) sh[tid] += sh[tid + o];
        __syncthreads();
    }
    if (tid == 0) {
        double lmean = sh[0] / (double)(BB * HWSZ);
        double ss = 0, sc = 0, rs = 0, rc = 0, ms = 0, mc = 0;
        for (int j = 0; j < NJOB; j++) {
            const float* o = g_job_out + j * 6;
            ss += (double)o[0] * o[1]; sc += o[1];
            rs += (double)o[2] * o[3]; rc += o[3];
            ms += (double)o[4] * o[5]; mc += o[5];
        }
        double lstd    = (sc > 0.0) ? ss / sc : 0.0;
        double lrank   = (rc > 0.0) ? rs / rc : 0.0;
        double lsmooth = (mc > 0.0) ? ms / mc : 0.0;
        double loss = (0.5 * lmean + 0.5 * lstd) + lrank + lsmooth;
        out[0] = (float)loss;
    }
}

extern "C" void kernel_launch(void* const* d_in, const int* in_sizes, int n_in,
                              void* d_out, int out_size) {
    const float* pred   = (const float*)d_in[0];
    const float* target = (const float*)d_in[1];
    const int*   lab14  = (const int*)d_in[2];
    const float* img1   = (const float*)d_in[3];
    const float* img2   = (const float*)d_in[4];

    cudaFuncSetAttribute(k_region, cudaFuncAttributeMaxDynamicSharedMemorySize,
                         4 * NWORDS * (int)sizeof(uint32_t));

    k_meanabs<<<NMEANBLK, 256>>>(pred, target, BB * HWSZ);
    k_region<<<NJOB, 512, 4 * NWORDS * sizeof(uint32_t)>>>(pred, lab14, img1, img2);
    k_final<<<1, 256>>>((float*)d_out);
}

// round 5
// speedup vs baseline: 2.6267x; 2.6267x over previous
#include <cuda_runtime.h>
#include <cstdint>

#define HH 512
#define WW 512
#define HWSZ (HH*WW)
#define BB 16
#define NJOB 48
#define NWORDS 8192   /* 512 rows * 16 words */
#define WPR 16
#define NMEANBLK 2048

__device__ uint32_t g_M [NJOB][NWORDS];
__device__ uint32_t g_E1[NJOB][NWORDS];
__device__ uint32_t g_E2[NJOB][NWORDS];
__device__ int      g_cnt[NJOB * 3];
__device__ double   g_acc[NJOB * 6];    // S, S2, SDX, SDY, CX, CY
__device__ double   g_mean_partial[NMEANBLK];
__device__ float    g_job_out[NJOB * 6];

__device__ __forceinline__ uint32_t rotl32(uint32_t x, int r) {
    return (x << r) | (x >> (32 - r));
}

// JAX threefry2x32 (20 rounds)
__device__ __forceinline__ void threefry(uint32_t k0, uint32_t k1,
                                         uint32_t x0, uint32_t x1,
                                         uint32_t &o0, uint32_t &o1) {
    uint32_t k2 = k0 ^ k1 ^ 0x1BD11BDAu;
    uint32_t a = x0 + k0, b = x1 + k1;
#define RND(r) { a += b; b = rotl32(b, r); b ^= a; }
    RND(13) RND(15) RND(26) RND(6)  a += k1; b += k2 + 1u;
    RND(17) RND(29) RND(16) RND(24) a += k2; b += k0 + 2u;
    RND(13) RND(15) RND(26) RND(6)  a += k0; b += k1 + 3u;
    RND(17) RND(29) RND(16) RND(24) a += k1; b += k2 + 4u;
    RND(13) RND(15) RND(26) RND(6)  a += k2; b += k0 + 5u;
#undef RND
    o0 = a; o1 = b;
}

// ---------------- zero accumulators ----------------
__global__ void k_zero() {
    int t = threadIdx.x;
    if (t < NJOB * 3) g_cnt[t] = 0;
    if (t < NJOB * 6) g_acc[t] = 0.0;
}

// ---------------- mean |pred - target| (float4) ----------------
__global__ void k_meanabs(const float4* __restrict__ p,
                          const float4* __restrict__ t, int n4) {
    __shared__ double sh[256];
    float a0 = 0.f, a1 = 0.f, a2 = 0.f, a3 = 0.f;
    int stride = gridDim.x * blockDim.x;
    for (int i = blockIdx.x * blockDim.x + threadIdx.x; i < n4; i += stride) {
        float4 x = p[i], y = t[i];
        a0 += fabsf(x.x - y.x); a1 += fabsf(x.y - y.y);
        a2 += fabsf(x.z - y.z); a3 += fabsf(x.w - y.w);
    }
    sh[threadIdx.x] = ((double)a0 + (double)a1) + ((double)a2 + (double)a3);
    __syncthreads();
    for (int o = 128; o > 0; o >>= 1) {
        if (threadIdx.x < o) sh[threadIdx.x] += sh[threadIdx.x + o];
        __syncthreads();
    }
    if (threadIdx.x == 0) g_mean_partial[blockIdx.x] = sh[0];
}

// ---------------- masks + erosions per 32-row strip ----------------
__global__ void __launch_bounds__(512)
k_mask(const int* __restrict__ lab14) {
    // block: (strip s, batch b). local rows: 36 (strip rows + 2 halo each side)
    __shared__ uint32_t Msm[3][576];
    __shared__ uint32_t Tb[576], E1s[576], Tb2[576];

    const int tid = threadIdx.x, lane = tid & 31, warp = tid >> 5;
    const int s = blockIdx.x, b = blockIdx.y;
    const int r0 = s * 32;
    const int* lab = lab14 + (size_t)b * HWSZ;

    // build 3 masks from one lab pass (out-of-range rows = all ones: inf-pad)
    for (int lw = warp; lw < 576; lw += 16) {
        int lr = lw >> 4, wc = lw & 15;
        int gr = r0 - 2 + lr;
        bool b5 = true, b8 = true, b13 = true;
        if (gr >= 0 && gr < HH) {
            int v = lab[gr * WW + (wc << 5) + lane];
            b5 = (v == 5); b8 = (v == 8); b13 = (v == 13);
        }
        uint32_t m5  = __ballot_sync(0xffffffffu, b5);
        uint32_t m8  = __ballot_sync(0xffffffffu, b8);
        uint32_t m13 = __ballot_sync(0xffffffffu, b13);
        if (lane == 0) { Msm[0][lw] = m5; Msm[1][lw] = m8; Msm[2][lw] = m13; }
    }
    __syncthreads();

    for (int li = 0; li < 3; li++) {
        const uint32_t* M = Msm[li];
        const int job = b * 3 + li;
        // horizontal erosion (edge pad = 1)
        for (int lw = tid; lw < 576; lw += 512) {
            int wc = lw & 15;
            uint32_t m = M[lw];
            uint32_t l = (m << 1) | (wc ? (M[lw - 1] >> 31) : 1u);
            uint32_t r = (m >> 1) | ((wc < 15) ? (M[lw + 1] << 31) : 0x80000000u);
            Tb[lw] = m & l & r;
        }
        __syncthreads();
        // vertical -> E1 for local rows 1..34; out-of-range rows = all ones
        for (int lw = tid; lw < 576; lw += 512) {
            int lr = lw >> 4;
            int gr = r0 - 2 + lr;
            uint32_t v;
            if (gr < 0 || gr >= HH)       v = 0xffffffffu;
            else if (lr >= 1 && lr <= 34) v = Tb[lw] & Tb[lw - 16] & Tb[lw + 16];
            else                          v = 0u;  // unused
            E1s[lw] = v;
        }
        __syncthreads();
        // second erosion: horizontal on E1
        for (int lw = tid; lw < 576; lw += 512) {
            int wc = lw & 15;
            uint32_t m = E1s[lw];
            uint32_t l = (m << 1) | (wc ? (E1s[lw - 1] >> 31) : 1u);
            uint32_t r = (m >> 1) | ((wc < 15) ? (E1s[lw + 1] << 31) : 0x80000000u);
            Tb2[lw] = m & l & r;
        }
        __syncthreads();
        // vertical -> E2 for strip rows, write out + count
        int c0 = 0, c1 = 0, c2 = 0;
        for (int lw = tid; lw < 576; lw += 512) {
            int lr = lw >> 4;
            if (lr >= 2 && lr <= 33) {
                uint32_t e2 = Tb2[lw] & Tb2[lw - 16] & Tb2[lw + 16];
                int gw = (r0 + lr - 2) * WPR + (lw & 15);
                uint32_t m = M[lw], e1 = E1s[lw];
                g_M[job][gw] = m; g_E1[job][gw] = e1; g_E2[job][gw] = e2;
                c0 += __popc(m); c1 += __popc(e1); c2 += __popc(e2);
            }
        }
        for (int o = 16; o; o >>= 1) {
            c0 += __shfl_down_sync(0xffffffffu, c0, o);
            c1 += __shfl_down_sync(0xffffffffu, c1, o);
            c2 += __shfl_down_sync(0xffffffffu, c2, o);
        }
        if (lane == 0) {
            atomicAdd(&g_cnt[job * 3 + 0], c0);
            atomicAdd(&g_cnt[job * 3 + 1], c1);
            atomicAdd(&g_cnt[job * 3 + 2], c2);
        }
        __syncthreads();
    }
}

// deterministic block reduce (512 threads / 16 warps)
__device__ double blockReduceD(double v, double* red) {
    int lane = threadIdx.x & 31, warp = threadIdx.x >> 5;
    for (int o = 16; o; o >>= 1) v += __shfl_down_sync(0xffffffffu, v, o);
    __syncthreads();
    if (lane == 0) red[warp] = v;
    __syncthreads();
    if (warp == 0) {
        double r = (lane < 16) ? red[lane] : 0.0;
        for (int o = 8; o; o >>= 1) r += __shfl_down_sync(0xffffffffu, r, o);
        if (lane == 0) red[0] = r;
    }
    __syncthreads();
    return red[0];
}

// ---------------- stats + smoothness per (strip, job) ----------------
__global__ void __launch_bounds__(512)
k_stats(const float* __restrict__ pred) {
    __shared__ double red[16];
    const int tid = threadIdx.x, lane = tid & 31, warp = tid >> 5;
    const int s = blockIdx.x, job = blockIdx.y;
    const int b = job / 3;

    const int n1c = g_cnt[job * 3 + 1];
    const int n2c = g_cnt[job * 3 + 2];
    const uint32_t* C1 = (n1c < 2) ? g_M[job] : g_E1[job];
    const uint32_t* C2 = (n2c < 3) ? C1 : g_E2[job];
    const float* P = pred + (size_t)b * HWSZ;

    const int base = s * 512;
    double sv = 0.0, s2 = 0.0, sdx = 0.0, sdy = 0.0;
    int cx = 0, cy = 0;
    for (int lw = warp; lw < 512; lw += 16) {
        int gw = base + lw;
        uint32_t word = C2[gw];
        if (!word) continue;
        bool in = (word >> lane) & 1u;
        if (!in) continue;
        int wc = gw & 15;
        int idx = (gw << 5) + lane;
        float v = P[idx];
        sv += (double)v; s2 += (double)v * (double)v;
        uint32_t right;
        if (lane < 31) right = (word >> (lane + 1)) & 1u;
        else           right = (wc < 15) ? (C2[gw + 1] & 1u) : 0u;
        if (right) { float vr = P[idx + 1];  sdx += (double)fabsf(vr - v); cx++; }
        uint32_t down = (gw < NWORDS - WPR) ? ((C2[gw + WPR] >> lane) & 1u) : 0u;
        if (down)  { float vd = P[idx + WW]; sdy += (double)fabsf(vd - v); cy++; }
    }
    double S   = blockReduceD(sv, red);
    double S2  = blockReduceD(s2, red);
    double SDX = blockReduceD(sdx, red);
    double SDY = blockReduceD(sdy, red);
    double CX  = blockReduceD((double)cx, red);
    double CY  = blockReduceD((double)cy, red);
    if (tid == 0) {
        atomicAdd(&g_acc[job * 6 + 0], S);
        atomicAdd(&g_acc[job * 6 + 1], S2);
        atomicAdd(&g_acc[job * 6 + 2], SDX);
        atomicAdd(&g_acc[job * 6 + 3], SDY);
        atomicAdd(&g_acc[job * 6 + 4], CX);
        atomicAdd(&g_acc[job * 6 + 5], CY);
    }
}

// ---------------- rank sampling + per-job finalize ----------------
__global__ void __launch_bounds__(512)
k_rank(const float* __restrict__ pred, const float* __restrict__ img1,
       const float* __restrict__ img2) {
    __shared__ int   pref[HH];
    __shared__ int   samp[200];
    __shared__ float pairbuf[200];

    const int tid = threadIdx.x;
    const int job = blockIdx.x;
    const int b = job / 3, li = job - 3 * b;
    const float tgts[3] = {0.077f, 0.227f, 0.348f};
    const float tgtcv = tgts[li];

    const int n_reg = g_cnt[job * 3 + 0];
    const int nE1   = g_cnt[job * 3 + 1];
    const int nE2   = g_cnt[job * 3 + 2];
    const uint32_t* C1 = (nE1 < 2) ? g_M[job] : g_E1[job];
    const int       n1 = (nE1 < 2) ? n_reg : nE1;
    const int       n2 = (nE2 < 3) ? n1 : nE2;
    const float* P = pred + (size_t)b * HWSZ;

    // row popcounts, one thread per row
    {
        int base = tid * WPR, c = 0;
#pragma unroll
        for (int k = 0; k < WPR; k++) c += __popc(C1[base + k]);
        pref[tid] = c;
    }
    __syncthreads();
    // Hillis-Steele inclusive scan over 512 rows
    for (int off = 1; off < HH; off <<= 1) {
        int v = pref[tid];
        int add = (tid >= off) ? pref[tid - off] : 0;
        __syncthreads();
        pref[tid] = v + add;
        __syncthreads();
    }

    // threefry sampling (JAX key path)
    if (n1 >= 1 && tid < 200) {
        uint32_t o0a, o1a, o0b, o1b, ka, kb;
        int i0, i1; bool first;
        if (job < 24) { i0 = 2 * job;      i1 = 2 * job + 1;  first = true;  }
        else          { i0 = 2 * job - 48; i1 = 2 * job - 47; first = false; }
        threefry(0u, 42u, (uint32_t)i0, (uint32_t)(48 + i0), o0a, o1a);
        threefry(0u, 42u, (uint32_t)i1, (uint32_t)(48 + i1), o0b, o1b);
        ka = first ? o0a : o1a;  kb = first ? o0b : o1b;
        uint32_t p00, p01, p10, p11;
        threefry(ka, kb, 0u, 2u, p00, p01);
        threefry(ka, kb, 1u, 3u, p10, p11);
        uint32_t qk0, qk1;
        if (tid < 100) { qk0 = p00; qk1 = p10; }
        else           { qk0 = p01; qk1 = p11; }
        int q = (tid < 100) ? tid : tid - 100;
        uint32_t b0, b1, bits;
        if (q < 50) { threefry(qk0, qk1, (uint32_t)q,        (uint32_t)(50 + q), b0, b1); bits = b0; }
        else        { threefry(qk0, qk1, (uint32_t)(q - 50), (uint32_t)q,        b0, b1); bits = b1; }
        float u = __uint_as_float((bits >> 9) | 0x3f800000u) - 1.0f;
        float r = 1.0f - u;
        int m = (int)ceilf((float)n1 * r);
        m = min(max(m, 1), n1);
        int lo = 0, hi = HH - 1;
        while (lo < hi) { int mid = (lo + hi) >> 1; if (pref[mid] >= m) hi = mid; else lo = mid + 1; }
        int row = lo;
        int rem = m - (row ? pref[row - 1] : 0);
        int base = row * WPR, col = 0;
        for (int kw = 0; kw < WPR; kw++) {
            uint32_t wv = C1[base + kw];
            int pc = __popc(wv);
            if (rem <= pc) {
                for (int z = 1; z < rem; z++) wv &= wv - 1;
                col = (kw << 5) + (__ffs(wv) - 1);
                break;
            }
            rem -= pc;
        }
        samp[tid] = row * WW + col;
    }
    __syncthreads();

    if (n1 >= 1 && tid < 100) {
        const float* T1 = img1 + (size_t)b * HWSZ;
        const float* T2 = img2 + (size_t)b * HWSZ;
        int ia = samp[tid], jb = samp[100 + tid];
        float xi = 0.5f * (1.0f - T1[ia]) + 0.5f * T2[ia];
        float xj = 0.5f * (1.0f - T1[jb]) + 0.5f * T2[jb];
        float d = xi - xj;
        float sg = (d > 0.0f) ? 1.0f : ((d < 0.0f) ? -1.0f : 0.0f);
        float pv = (ia != jb && sg != 0.0f) ? 1.0f : 0.0f;
        float hinge = fmaxf(0.0f, -(P[ia] - P[jb]) * sg);
        pairbuf[tid] = hinge * pv;
        pairbuf[100 + tid] = pv;
    }
    __syncthreads();

    if (tid == 0) {
        const double* A = g_acc + job * 6;
        double S = A[0], S2 = A[1], SDX = A[2], SDY = A[3], CX = A[4], CY = A[5];
        double n2s = (n2 > 1) ? (double)n2 : 1.0;
        double mu = S / n2s;
        double var = S2 / n2s - mu * mu;
        if (var < 0.0) var = 0.0;
        float cv = (float)(sqrt(var) / (fabs(mu) + 1e-6));
        float sv = fabsf(cv - tgtcv);
        float svd = (n_reg >= 3 && n2 >= 3) ? 1.0f : 0.0f;

        double mean_x = SDX / ((CX > 1.0) ? CX : 1.0);
        double mean_y = SDY / ((CY > 1.0) ? CY : 1.0);
        float hx = (CX > 0.0) ? 1.0f : 0.0f;
        float hy = (CY > 0.0) ? 1.0f : 0.0f;
        float npres = hx + hy;
        float mval = (float)((mean_x * hx + mean_y * hy) / ((npres > 1.0f) ? npres : 1.0f));
        float mvd = (n_reg >= 3 && n2 >= 3 && npres > 0.0f) ? 1.0f : 0.0f;

        float hs = 0.0f, npv = 0.0f;
        if (n1 >= 1) {
            for (int i = 0; i < 100; i++) { hs += pairbuf[i]; npv += pairbuf[100 + i]; }
        }
        float rv = hs / fmaxf(npv, 1.0f);
        float rvd = (n_reg >= 2 && n1 >= 2 && npv > 0.0f) ? 1.0f : 0.0f;

        float* o = g_job_out + job * 6;
        o[0] = sv;   o[1] = svd;
        o[2] = rv;   o[3] = rvd;
        o[4] = mval; o[5] = mvd;
    }
}

// ---------------- finalize ----------------
__global__ void k_final(float* __restrict__ out) {
    __shared__ double sh[256];
    int tid = threadIdx.x;
    double s = 0.0;
    for (int i = tid; i < NMEANBLK; i += 256) s += g_mean_partial[i];
    sh[tid] = s;
    __syncthreads();
    for (int o = 128; o > 0; o >>= 1) {
        if (tid < o) sh[tid] += sh[tid + o];
        __syncthreads();
    }
    if (tid == 0) {
        double lmean = sh[0] / (double)(BB * HWSZ);
        double ss = 0, sc = 0, rs = 0, rc = 0, ms = 0, mc = 0;
        for (int j = 0; j < NJOB; j++) {
            const float* o = g_job_out + j * 6;
            ss += (double)o[0] * o[1]; sc += o[1];
            rs += (double)o[2] * o[3]; rc += o[3];
            ms += (double)o[4] * o[5]; mc += o[5];
        }
        double lstd    = (sc > 0.0) ? ss / sc : 0.0;
        double lrank   = (rc > 0.0) ? rs / rc : 0.0;
        double lsmooth = (mc > 0.0) ? ms / mc : 0.0;
        double loss = (0.5 * lmean + 0.5 * lstd) + lrank + lsmooth;
        out[0] = (float)loss;
    }
}

extern "C" void kernel_launch(void* const* d_in, const int* in_sizes, int n_in,
                              void* d_out, int out_size) {
    const float* pred   = (const float*)d_in[0];
    const float* target = (const float*)d_in[1];
    const int*   lab14  = (const int*)d_in[2];
    const float* img1   = (const float*)d_in[3];
    const float* img2   = (const float*)d_in[4];

    k_zero<<<1, 512>>>();
    k_meanabs<<<NMEANBLK, 256>>>((const float4*)pred, (const float4*)target,
                                 BB * HWSZ / 4);
    k_mask<<<dim3(16, 16), 512>>>(lab14);
    k_stats<<<dim3(16, NJOB), 512>>>(pred);
    k_rank<<<NJOB, 512>>>(pred, img1, img2);
    k_final<<<1, 256>>>((float*)d_out);
}

// round 7
// speedup vs baseline: 6.0426x; 2.3004x over previous
#include <cuda_runtime.h>
#include <cstdint>

#define HH 512
#define WW 512
#define HWSZ (HH*WW)
#define BB 16
#define NJOB 48
#define NWORDS 8192   /* 512 rows * 16 words */
#define WPR 16
#define NMEANBLK 2048

__device__ uint32_t g_M [NJOB][NWORDS];
__device__ uint32_t g_E1[NJOB][NWORDS];
__device__ uint32_t g_E2[NJOB][NWORDS];
__device__ int      g_cnt[NJOB * 3];
__device__ double   g_acc[NJOB * 6];    // S, S2, SDX, SDY, CX, CY
__device__ double   g_mean_partial[NMEANBLK];
__device__ float    g_job_out[NJOB * 6];

__device__ __forceinline__ uint32_t rotl32(uint32_t x, int r) {
    return (x << r) | (x >> (32 - r));
}

// JAX threefry2x32 (20 rounds)
__device__ __forceinline__ void threefry(uint32_t k0, uint32_t k1,
                                         uint32_t x0, uint32_t x1,
                                         uint32_t &o0, uint32_t &o1) {
    uint32_t k2 = k0 ^ k1 ^ 0x1BD11BDAu;
    uint32_t a = x0 + k0, b = x1 + k1;
#define RND(r) { a += b; b = rotl32(b, r); b ^= a; }
    RND(13) RND(15) RND(26) RND(6)  a += k1; b += k2 + 1u;
    RND(17) RND(29) RND(16) RND(24) a += k2; b += k0 + 2u;
    RND(13) RND(15) RND(26) RND(6)  a += k0; b += k1 + 3u;
    RND(17) RND(29) RND(16) RND(24) a += k1; b += k2 + 4u;
    RND(13) RND(15) RND(26) RND(6)  a += k2; b += k0 + 5u;
#undef RND
    o0 = a; o1 = b;
}

// ---------------- zero accumulators ----------------
__global__ void k_zero() {
    int t = threadIdx.x;
    if (t < NJOB * 3) g_cnt[t] = 0;
    if (t < NJOB * 6) g_acc[t] = 0.0;
}

// ---------------- mean |pred - target| (float4) ----------------
__global__ void k_meanabs(const float4* __restrict__ p,
                          const float4* __restrict__ t, int n4) {
    __shared__ double sh[256];
    float a0 = 0.f, a1 = 0.f, a2 = 0.f, a3 = 0.f;
    int stride = gridDim.x * blockDim.x;
    for (int i = blockIdx.x * blockDim.x + threadIdx.x; i < n4; i += stride) {
        float4 x = p[i], y = t[i];
        a0 += fabsf(x.x - y.x); a1 += fabsf(x.y - y.y);
        a2 += fabsf(x.z - y.z); a3 += fabsf(x.w - y.w);
    }
    sh[threadIdx.x] = ((double)a0 + (double)a1) + ((double)a2 + (double)a3);
    __syncthreads();
    for (int o = 128; o > 0; o >>= 1) {
        if (threadIdx.x < o) sh[threadIdx.x] += sh[threadIdx.x + o];
        __syncthreads();
    }
    if (threadIdx.x == 0) g_mean_partial[blockIdx.x] = sh[0];
}

// ---------------- masks + erosions per 32-row strip ----------------
__global__ void __launch_bounds__(512)
k_mask(const int* __restrict__ lab14) {
    __shared__ uint32_t Msm[3][576];
    __shared__ uint32_t Tb[576], E1s[576], Tb2[576];

    const int tid = threadIdx.x, lane = tid & 31, warp = tid >> 5;
    const int s = blockIdx.x, b = blockIdx.y;
    const int r0 = s * 32;
    const int* lab = lab14 + (size_t)b * HWSZ;

    for (int lw = warp; lw < 576; lw += 16) {
        int lr = lw >> 4, wc = lw & 15;
        int gr = r0 - 2 + lr;
        bool b5 = true, b8 = true, b13 = true;
        if (gr >= 0 && gr < HH) {
            int v = lab[gr * WW + (wc << 5) + lane];
            b5 = (v == 5); b8 = (v == 8); b13 = (v == 13);
        }
        uint32_t m5  = __ballot_sync(0xffffffffu, b5);
        uint32_t m8  = __ballot_sync(0xffffffffu, b8);
        uint32_t m13 = __ballot_sync(0xffffffffu, b13);
        if (lane == 0) { Msm[0][lw] = m5; Msm[1][lw] = m8; Msm[2][lw] = m13; }
    }
    __syncthreads();

    for (int li = 0; li < 3; li++) {
        const uint32_t* M = Msm[li];
        const int job = b * 3 + li;
        for (int lw = tid; lw < 576; lw += 512) {
            int wc = lw & 15;
            uint32_t m = M[lw];
            uint32_t l = (m << 1) | (wc ? (M[lw - 1] >> 31) : 1u);
            uint32_t r = (m >> 1) | ((wc < 15) ? (M[lw + 1] << 31) : 0x80000000u);
            Tb[lw] = m & l & r;
        }
        __syncthreads();
        for (int lw = tid; lw < 576; lw += 512) {
            int lr = lw >> 4;
            int gr = r0 - 2 + lr;
            uint32_t v;
            if (gr < 0 || gr >= HH)       v = 0xffffffffu;
            else if (lr >= 1 && lr <= 34) v = Tb[lw] & Tb[lw - 16] & Tb[lw + 16];
            else                          v = 0u;
            E1s[lw] = v;
        }
        __syncthreads();
        for (int lw = tid; lw < 576; lw += 512) {
            int wc = lw & 15;
            uint32_t m = E1s[lw];
            uint32_t l = (m << 1) | (wc ? (E1s[lw - 1] >> 31) : 1u);
            uint32_t r = (m >> 1) | ((wc < 15) ? (E1s[lw + 1] << 31) : 0x80000000u);
            Tb2[lw] = m & l & r;
        }
        __syncthreads();
        int c0 = 0, c1 = 0, c2 = 0;
        for (int lw = tid; lw < 576; lw += 512) {
            int lr = lw >> 4;
            if (lr >= 2 && lr <= 33) {
                uint32_t e2 = Tb2[lw] & Tb2[lw - 16] & Tb2[lw + 16];
                int gw = (r0 + lr - 2) * WPR + (lw & 15);
                uint32_t m = Msm[li][lw], e1 = E1s[lw];
                g_M[job][gw] = m; g_E1[job][gw] = e1; g_E2[job][gw] = e2;
                c0 += __popc(m); c1 += __popc(e1); c2 += __popc(e2);
            }
        }
        for (int o = 16; o; o >>= 1) {
            c0 += __shfl_down_sync(0xffffffffu, c0, o);
            c1 += __shfl_down_sync(0xffffffffu, c1, o);
            c2 += __shfl_down_sync(0xffffffffu, c2, o);
        }
        if (lane == 0) {
            atomicAdd(&g_cnt[job * 3 + 0], c0);
            atomicAdd(&g_cnt[job * 3 + 1], c1);
            atomicAdd(&g_cnt[job * 3 + 2], c2);
        }
        __syncthreads();
    }
}

// ---------------- dense stats + smoothness per (strip, batch), all 3 labels ----------------
#define SROWS 16
#define MSKW ((SROWS + 1) * WPR)   /* 272 words per label */
__global__ void __launch_bounds__(512)
k_stats(const float* __restrict__ pred) {
    __shared__ float    sp[SROWS + 1][WW];   // 17 rows of pred
    __shared__ uint32_t msk[3][MSKW];        // C2 bitmask strip + down halo
    __shared__ double   wred[16][18];

    const int tid = threadIdx.x, lane = tid & 31, warp = tid >> 5;
    const int s = blockIdx.x, b = blockIdx.y;
    const int r0 = s * SROWS;
    const float* P = pred + (size_t)b * HWSZ;

    // stage pred rows (17 coalesced row loads)
#pragma unroll
    for (int lr = 0; lr <= SROWS; lr++) {
        int gr = r0 + lr;
        sp[lr][tid] = (gr < HH) ? P[gr * WW + tid] : 0.0f;
    }

    // stage C2 mask words for 3 labels (3*272 = 816 words, grid-stride over 512 thr)
    for (int i = tid; i < 3 * MSKW; i += 512) {
        int l = i / MSKW;
        int rem = i - l * MSKW;
        int lr = rem / WPR, wc = rem - lr * WPR;
        int job = b * 3 + l;
        int n1c = g_cnt[job * 3 + 1];
        int n2c = g_cnt[job * 3 + 2];
        const uint32_t* C2 = (n2c < 3)
            ? ((n1c < 2) ? g_M[job] : g_E1[job])
            : g_E2[job];
        int gr = r0 + lr;
        msk[l][rem] = (gr < HH) ? C2[gr * WPR + wc] : 0u;
    }
    __syncthreads();

    float accS[3]  = {0.f, 0.f, 0.f}, accS2[3] = {0.f, 0.f, 0.f};
    float accDX[3] = {0.f, 0.f, 0.f}, accDY[3] = {0.f, 0.f, 0.f};
    int   accCX[3] = {0, 0, 0},       accCY[3] = {0, 0, 0};

    const int wi  = tid >> 5;             // word index of this column
    const int c1  = tid + 1;
    const int wi1 = c1 >> 5, sh1 = c1 & 31;
    const bool hasR = (tid < WW - 1);

#pragma unroll
    for (int lr = 0; lr < SROWS; lr++) {
        float v  = sp[lr][tid];
        float vr = hasR ? sp[lr][tid + 1] : 0.0f;
        float vd = sp[lr + 1][tid];
        float adx = fabsf(vr - v);
        float ady = fabsf(vd - v);
#pragma unroll
        for (int l = 0; l < 3; l++) {
            uint32_t w0 = msk[l][lr * WPR + wi];
            uint32_t in = (w0 >> lane) & 1u;
            if (in) {
                accS[l]  += v;
                accS2[l] += v * v;
                uint32_t rb = hasR ? ((msk[l][lr * WPR + wi1] >> sh1) & 1u) : 0u;
                uint32_t db = (msk[l][(lr + 1) * WPR + wi] >> lane) & 1u;
                if (rb) { accDX[l] += adx; accCX[l]++; }
                if (db) { accDY[l] += ady; accCY[l]++; }
            }
        }
    }

    // warp reduce 18 values, then per-block sum + atomic
#pragma unroll
    for (int l = 0; l < 3; l++) {
#pragma unroll
        for (int o = 16; o; o >>= 1) {
            accS[l]  += __shfl_down_sync(0xffffffffu, accS[l],  o);
            accS2[l] += __shfl_down_sync(0xffffffffu, accS2[l], o);
            accDX[l] += __shfl_down_sync(0xffffffffu, accDX[l], o);
            accDY[l] += __shfl_down_sync(0xffffffffu, accDY[l], o);
            accCX[l] += __shfl_down_sync(0xffffffffu, accCX[l], o);
            accCY[l] += __shfl_down_sync(0xffffffffu, accCY[l], o);
        }
    }
    if (lane == 0) {
#pragma unroll
        for (int l = 0; l < 3; l++) {
            wred[warp][l * 6 + 0] = (double)accS[l];
            wred[warp][l * 6 + 1] = (double)accS2[l];
            wred[warp][l * 6 + 2] = (double)accDX[l];
            wred[warp][l * 6 + 3] = (double)accDY[l];
            wred[warp][l * 6 + 4] = (double)accCX[l];
            wred[warp][l * 6 + 5] = (double)accCY[l];
        }
    }
    __syncthreads();
    if (tid < 18) {
        double sum = 0.0;
#pragma unroll
        for (int w = 0; w < 16; w++) sum += wred[w][tid];
        int l = tid / 6, k = tid - l * 6;
        atomicAdd(&g_acc[(b * 3 + l) * 6 + k], sum);
    }
}

// ---------------- rank sampling + per-job finalize ----------------
__global__ void __launch_bounds__(512)
k_rank(const float* __restrict__ pred, const float* __restrict__ img1,
       const float* __restrict__ img2) {
    __shared__ int   pref[HH];
    __shared__ int   samp[200];
    __shared__ float pairbuf[200];

    const int tid = threadIdx.x;
    const int job = blockIdx.x;
    const int b = job / 3, li = job - 3 * b;
    const float tgts[3] = {0.077f, 0.227f, 0.348f};
    const float tgtcv = tgts[li];

    const int n_reg = g_cnt[job * 3 + 0];
    const int nE1   = g_cnt[job * 3 + 1];
    const int nE2   = g_cnt[job * 3 + 2];
    const uint32_t* C1 = (nE1 < 2) ? g_M[job] : g_E1[job];
    const int       n1 = (nE1 < 2) ? n_reg : nE1;
    const int       n2 = (nE2 < 3) ? n1 : nE2;
    const float* P = pred + (size_t)b * HWSZ;

    {
        int base = tid * WPR, c = 0;
#pragma unroll
        for (int k = 0; k < WPR; k++) c += __popc(C1[base + k]);
        pref[tid] = c;
    }
    __syncthreads();
    for (int off = 1; off < HH; off <<= 1) {
        int v = pref[tid];
        int add = (tid >= off) ? pref[tid - off] : 0;
        __syncthreads();
        pref[tid] = v + add;
        __syncthreads();
    }

    if (n1 >= 1 && tid < 200) {
        uint32_t o0a, o1a, o0b, o1b, ka, kb;
        int i0, i1; bool first;
        if (job < 24) { i0 = 2 * job;      i1 = 2 * job + 1;  first = true;  }
        else          { i0 = 2 * job - 48; i1 = 2 * job - 47; first = false; }
        threefry(0u, 42u, (uint32_t)i0, (uint32_t)(48 + i0), o0a, o1a);
        threefry(0u, 42u, (uint32_t)i1, (uint32_t)(48 + i1), o0b, o1b);
        ka = first ? o0a : o1a;  kb = first ? o0b : o1b;
        uint32_t p00, p01, p10, p11;
        threefry(ka, kb, 0u, 2u, p00, p01);
        threefry(ka, kb, 1u, 3u, p10, p11);
        uint32_t qk0, qk1;
        if (tid < 100) { qk0 = p00; qk1 = p10; }
        else           { qk0 = p01; qk1 = p11; }
        int q = (tid < 100) ? tid : tid - 100;
        uint32_t b0, b1, bits;
        if (q < 50) { threefry(qk0, qk1, (uint32_t)q,        (uint32_t)(50 + q), b0, b1); bits = b0; }
        else        { threefry(qk0, qk1, (uint32_t)(q - 50), (uint32_t)q,        b0, b1); bits = b1; }
        float u = __uint_as_float((bits >> 9) | 0x3f800000u) - 1.0f;
        float r = 1.0f - u;
        int m = (int)ceilf((float)n1 * r);
        m = min(max(m, 1), n1);
        int lo = 0, hi = HH - 1;
        while (lo < hi) { int mid = (lo + hi) >> 1; if (pref[mid] >= m) hi = mid; else lo = mid + 1; }
        int row = lo;
        int rem = m - (row ? pref[row - 1] : 0);
        int base = row * WPR, col = 0;
        for (int kw = 0; kw < WPR; kw++) {
            uint32_t wv = C1[base + kw];
            int pc = __popc(wv);
            if (rem <= pc) {
                for (int z = 1; z < rem; z++) wv &= wv - 1;
                col = (kw << 5) + (__ffs(wv) - 1);
                break;
            }
            rem -= pc;
        }
        samp[tid] = row * WW + col;
    }
    __syncthreads();

    if (n1 >= 1 && tid < 100) {
        const float* T1 = img1 + (size_t)b * HWSZ;
        const float* T2 = img2 + (size_t)b * HWSZ;
        int ia = samp[tid], jb = samp[100 + tid];
        float xi = 0.5f * (1.0f - T1[ia]) + 0.5f * T2[ia];
        float xj = 0.5f * (1.0f - T1[jb]) + 0.5f * T2[jb];
        float d = xi - xj;
        float sg = (d > 0.0f) ? 1.0f : ((d < 0.0f) ? -1.0f : 0.0f);
        float pv = (ia != jb && sg != 0.0f) ? 1.0f : 0.0f;
        float hinge = fmaxf(0.0f, -(P[ia] - P[jb]) * sg);
        pairbuf[tid] = hinge * pv;
        pairbuf[100 + tid] = pv;
    }
    __syncthreads();

    if (tid == 0) {
        const double* A = g_acc + job * 6;
        double S = A[0], S2 = A[1], SDX = A[2], SDY = A[3], CX = A[4], CY = A[5];
        double n2s = (n2 > 1) ? (double)n2 : 1.0;
        double mu = S / n2s;
        double var = S2 / n2s - mu * mu;
        if (var < 0.0) var = 0.0;
        float cv = (float)(sqrt(var) / (fabs(mu) + 1e-6));
        float sv = fabsf(cv - tgtcv);
        float svd = (n_reg >= 3 && n2 >= 3) ? 1.0f : 0.0f;

        double mean_x = SDX / ((CX > 1.0) ? CX : 1.0);
        double mean_y = SDY / ((CY > 1.0) ? CY : 1.0);
        float hx = (CX > 0.0) ? 1.0f : 0.0f;
        float hy = (CY > 0.0) ? 1.0f : 0.0f;
        float npres = hx + hy;
        float mval = (float)((mean_x * hx + mean_y * hy) / ((npres > 1.0f) ? npres : 1.0f));
        float mvd = (n_reg >= 3 && n2 >= 3 && npres > 0.0f) ? 1.0f : 0.0f;

        float hs = 0.0f, npv = 0.0f;
        if (n1 >= 1) {
            for (int i = 0; i < 100; i++) { hs += pairbuf[i]; npv += pairbuf[100 + i]; }
        }
        float rv = hs / fmaxf(npv, 1.0f);
        float rvd = (n_reg >= 2 && n1 >= 2 && npv > 0.0f) ? 1.0f : 0.0f;

        float* o = g_job_out + job * 6;
        o[0] = sv;   o[1] = svd;
        o[2] = rv;   o[3] = rvd;
        o[4] = mval; o[5] = mvd;
    }
}

// ---------------- finalize ----------------
__global__ void k_final(float* __restrict__ out) {
    __shared__ double sh[256];
    int tid = threadIdx.x;
    double s = 0.0;
    for (int i = tid; i < NMEANBLK; i += 256) s += g_mean_partial[i];
    sh[tid] = s;
    __syncthreads();
    for (int o = 128; o > 0; o >>= 1) {
        if (tid < o) sh[tid] += sh[tid + o];
        __syncthreads();
    }
    if (tid == 0) {
        double lmean = sh[0] / (double)(BB * HWSZ);
        double ss = 0, sc = 0, rs = 0, rc = 0, ms = 0, mc = 0;
        for (int j = 0; j < NJOB; j++) {
            const float* o = g_job_out + j * 6;
            ss += (double)o[0] * o[1]; sc += o[1];
            rs += (double)o[2] * o[3]; rc += o[3];
            ms += (double)o[4] * o[5]; mc += o[5];
        }
        double lstd    = (sc > 0.0) ? ss / sc : 0.0;
        double lrank   = (rc > 0.0) ? rs / rc : 0.0;
        double lsmooth = (mc > 0.0) ? ms / mc : 0.0;
        double loss = (0.5 * lmean + 0.5 * lstd) + lrank + lsmooth;
        out[0] = (float)loss;
    }
}

extern "C" void kernel_launch(void* const* d_in, const int* in_sizes, int n_in,
                              void* d_out, int out_size) {
    const float* pred   = (const float*)d_in[0];
    const float* target = (const float*)d_in[1];
    const int*   lab14  = (const int*)d_in[2];
    const float* img1   = (const float*)d_in[3];
    const float* img2   = (const float*)d_in[4];

    k_zero<<<1, 512>>>();
    k_meanabs<<<NMEANBLK, 256>>>((const float4*)pred, (const float4*)target,
                                 BB * HWSZ / 4);
    k_mask<<<dim3(16, 16), 512>>>(lab14);
    k_stats<<<dim3(HH / SROWS, BB), 512>>>(pred);
    k_rank<<<NJOB, 512>>>(pred, img1, img2);
    k_final<<<1, 256>>>((float*)d_out);
}

// round 11
// speedup vs baseline: 8.1569x; 1.3499x over previous
#include <cuda_runtime.h>
#include <cstdint>

#define HH 512
#define WW 512
#define HWSZ (HH*WW)
#define BB 16
#define NJOB 48
#define NWORDS 8192   /* 512 rows * 16 words */
#define WPR 16
#define NSTRIP16 32   /* k_stats strips (16 rows) */
#define NSTRIP32 16   /* k_mask strips (32 rows) */

__device__ uint32_t g_M [NJOB][NWORDS];
__device__ uint32_t g_E1[NJOB][NWORDS];
__device__ uint32_t g_E2[NJOB][NWORDS];
__device__ int      g_cnts[NJOB][3][NSTRIP32];   // per-strip counts (no atomics)
__device__ double   g_accs[NJOB][6][NSTRIP16];   // per-strip stat sums (no atomics)
__device__ double   g_mean_partial[NSTRIP16 * BB];
__device__ float    g_job_out[NJOB * 6];

__device__ __forceinline__ uint32_t rotl32(uint32_t x, int r) {
    return (x << r) | (x >> (32 - r));
}

// JAX threefry2x32 (20 rounds)
__device__ __forceinline__ void threefry(uint32_t k0, uint32_t k1,
                                         uint32_t x0, uint32_t x1,
                                         uint32_t &o0, uint32_t &o1) {
    uint32_t k2 = k0 ^ k1 ^ 0x1BD11BDAu;
    uint32_t a = x0 + k0, b = x1 + k1;
#define RND(r) { a += b; b = rotl32(b, r); b ^= a; }
    RND(13) RND(15) RND(26) RND(6)  a += k1; b += k2 + 1u;
    RND(17) RND(29) RND(16) RND(24) a += k2; b += k0 + 2u;
    RND(13) RND(15) RND(26) RND(6)  a += k0; b += k1 + 3u;
    RND(17) RND(29) RND(16) RND(24) a += k1; b += k2 + 4u;
    RND(13) RND(15) RND(26) RND(6)  a += k2; b += k0 + 5u;
#undef RND
    o0 = a; o1 = b;
}

// ---------------- masks + erosions, 3 labels per sweep ----------------
__global__ void __launch_bounds__(512)
k_mask(const int* __restrict__ lab14) {
    __shared__ uint32_t Msm[3][576];
    __shared__ uint32_t Tb[3][576];
    __shared__ uint32_t E1s[3][576];
    __shared__ int      wred[16][9];

    const int tid = threadIdx.x, lane = tid & 31, warp = tid >> 5;
    const int s = blockIdx.x, b = blockIdx.y;
    const int r0 = s * 32;
    const int* lab = lab14 + (size_t)b * HWSZ;

    // build 3 masks from one lab pass (out-of-range rows = all ones: inf-pad)
    for (int lw = warp; lw < 576; lw += 16) {
        int lr = lw >> 4, wc = lw & 15;
        int gr = r0 - 2 + lr;
        bool b5 = true, b8 = true, b13 = true;
        if (gr >= 0 && gr < HH) {
            int v = lab[gr * WW + (wc << 5) + lane];
            b5 = (v == 5); b8 = (v == 8); b13 = (v == 13);
        }
        uint32_t m5  = __ballot_sync(0xffffffffu, b5);
        uint32_t m8  = __ballot_sync(0xffffffffu, b8);
        uint32_t m13 = __ballot_sync(0xffffffffu, b13);
        if (lane == 0) { Msm[0][lw] = m5; Msm[1][lw] = m8; Msm[2][lw] = m13; }
    }
    __syncthreads();

    // horizontal erosion, all 3 labels
    for (int lw = tid; lw < 576; lw += 512) {
        int wc = lw & 15;
#pragma unroll
        for (int l = 0; l < 3; l++) {
            uint32_t m = Msm[l][lw];
            uint32_t lb = (m << 1) | (wc ? (Msm[l][lw - 1] >> 31) : 1u);
            uint32_t rb = (m >> 1) | ((wc < 15) ? (Msm[l][lw + 1] << 31) : 0x80000000u);
            Tb[l][lw] = m & lb & rb;
        }
    }
    __syncthreads();
    // vertical -> E1 (out-of-range rows = all ones)
    for (int lw = tid; lw < 576; lw += 512) {
        int lr = lw >> 4;
        int gr = r0 - 2 + lr;
#pragma unroll
        for (int l = 0; l < 3; l++) {
            uint32_t v;
            if (gr < 0 || gr >= HH)       v = 0xffffffffu;
            else if (lr >= 1 && lr <= 34) v = Tb[l][lw] & Tb[l][lw - 16] & Tb[l][lw + 16];
            else                          v = 0u;
            E1s[l][lw] = v;
        }
    }
    __syncthreads();
    // horizontal on E1 -> Tb (reuse)
    for (int lw = tid; lw < 576; lw += 512) {
        int wc = lw & 15;
#pragma unroll
        for (int l = 0; l < 3; l++) {
            uint32_t m = E1s[l][lw];
            uint32_t lb = (m << 1) | (wc ? (E1s[l][lw - 1] >> 31) : 1u);
            uint32_t rb = (m >> 1) | ((wc < 15) ? (E1s[l][lw + 1] << 31) : 0x80000000u);
            Tb[l][lw] = m & lb & rb;
        }
    }
    __syncthreads();
    // vertical -> E2, write out + count
    int cnt[9] = {0,0,0,0,0,0,0,0,0};
    for (int lw = tid; lw < 576; lw += 512) {
        int lr = lw >> 4;
        if (lr >= 2 && lr <= 33) {
            int gw = (r0 + lr - 2) * WPR + (lw & 15);
#pragma unroll
            for (int l = 0; l < 3; l++) {
                uint32_t e2 = Tb[l][lw] & Tb[l][lw - 16] & Tb[l][lw + 16];
                uint32_t m = Msm[l][lw], e1 = E1s[l][lw];
                int job = b * 3 + l;
                g_M[job][gw] = m; g_E1[job][gw] = e1; g_E2[job][gw] = e2;
                cnt[l * 3 + 0] += __popc(m);
                cnt[l * 3 + 1] += __popc(e1);
                cnt[l * 3 + 2] += __popc(e2);
            }
        }
    }
#pragma unroll
    for (int k = 0; k < 9; k++)
#pragma unroll
        for (int o = 16; o; o >>= 1)
            cnt[k] += __shfl_down_sync(0xffffffffu, cnt[k], o);
    if (lane == 0)
#pragma unroll
        for (int k = 0; k < 9; k++) wred[warp][k] = cnt[k];
    __syncthreads();
    if (tid < 9) {
        int sum = 0;
#pragma unroll
        for (int w = 0; w < 16; w++) sum += wred[w][tid];
        int l = tid / 3, c = tid - l * 3;
        g_cnts[b * 3 + l][c][s] = sum;
    }
}

// ---------------- dense stats + smooth + fused mean|pred-target| ----------------
#define SROWS 16
#define MSKW ((SROWS + 1) * WPR)   /* 272 words per label */
__global__ void __launch_bounds__(512)
k_stats(const float* __restrict__ pred, const float* __restrict__ target) {
    __shared__ float    sp[SROWS + 1][WW];   // 17 rows of pred
    __shared__ uint32_t msk[3][MSKW];        // C2 bitmask strip + down halo
    __shared__ double   wred[16][19];
    __shared__ int      sel[3];              // 0=M, 1=E1, 2=E2

    const int tid = threadIdx.x, lane = tid & 31, warp = tid >> 5;
    const int s = blockIdx.x, b = blockIdx.y;
    const int r0 = s * SROWS;
    const float* P = pred   + (size_t)b * HWSZ;
    const float* T = target + (size_t)b * HWSZ;

    // select C2 source per label (sum per-strip counts)
    if (tid < 3) {
        int job = b * 3 + tid;
        int n1c = 0, n2c = 0;
#pragma unroll
        for (int k = 0; k < NSTRIP32; k++) {
            n1c += g_cnts[job][1][k];
            n2c += g_cnts[job][2][k];
        }
        sel[tid] = (n2c >= 3) ? 2 : ((n1c >= 2) ? 1 : 0);
    }

    // stage pred rows + accumulate mean|diff| (17 coalesced rows; mean over 16)
    float amean = 0.0f;
#pragma unroll
    for (int lr = 0; lr <= SROWS; lr++) {
        int gr = r0 + lr;
        float v = (gr < HH) ? P[gr * WW + tid] : 0.0f;
        sp[lr][tid] = v;
        if (lr < SROWS) amean += fabsf(v - T[gr * WW + tid]);
    }
    __syncthreads();

    // stage C2 mask words for 3 labels
    for (int i = tid; i < 3 * MSKW; i += 512) {
        int l = i / MSKW;
        int rem = i - l * MSKW;
        int lr = rem / WPR, wc = rem - lr * WPR;
        int job = b * 3 + l;
        int sl = sel[l];
        const uint32_t* C2 = (sl == 2) ? g_E2[job] : ((sl == 1) ? g_E1[job] : g_M[job]);
        int gr = r0 + lr;
        msk[l][rem] = (gr < HH) ? C2[gr * WPR + wc] : 0u;
    }
    __syncthreads();

    float accS[3]  = {0.f, 0.f, 0.f}, accS2[3] = {0.f, 0.f, 0.f};
    float accDX[3] = {0.f, 0.f, 0.f}, accDY[3] = {0.f, 0.f, 0.f};
    int   accCX[3] = {0, 0, 0},       accCY[3] = {0, 0, 0};

    const int wi  = tid >> 5;
    const int c1  = tid + 1;
    const int wi1 = c1 >> 5, sh1 = c1 & 31;
    const bool hasR = (tid < WW - 1);

#pragma unroll
    for (int lr = 0; lr < SROWS; lr++) {
        float v  = sp[lr][tid];
        float vr = hasR ? sp[lr][tid + 1] : 0.0f;
        float vd = sp[lr + 1][tid];
        float adx = fabsf(vr - v);
        float ady = fabsf(vd - v);
#pragma unroll
        for (int l = 0; l < 3; l++) {
            uint32_t w0 = msk[l][lr * WPR + wi];
            uint32_t in = (w0 >> lane) & 1u;
            if (in) {
                accS[l]  += v;
                accS2[l] += v * v;
                uint32_t rb = hasR ? ((msk[l][lr * WPR + wi1] >> sh1) & 1u) : 0u;
                uint32_t db = (msk[l][(lr + 1) * WPR + wi] >> lane) & 1u;
                if (rb) { accDX[l] += adx; accCX[l]++; }
                if (db) { accDY[l] += ady; accCY[l]++; }
            }
        }
    }

    // warp reduce 18 stat values + mean
#pragma unroll
    for (int l = 0; l < 3; l++) {
#pragma unroll
        for (int o = 16; o; o >>= 1) {
            accS[l]  += __shfl_down_sync(0xffffffffu, accS[l],  o);
            accS2[l] += __shfl_down_sync(0xffffffffu, accS2[l], o);
            accDX[l] += __shfl_down_sync(0xffffffffu, accDX[l], o);
            accDY[l] += __shfl_down_sync(0xffffffffu, accDY[l], o);
            accCX[l] += __shfl_down_sync(0xffffffffu, accCX[l], o);
            accCY[l] += __shfl_down_sync(0xffffffffu, accCY[l], o);
        }
    }
    double dm = (double)amean;
    // deterministic per-warp double reduce of mean via shfl on double
    for (int o = 16; o; o >>= 1) dm += __shfl_down_sync(0xffffffffu, dm, o);

    if (lane == 0) {
#pragma unroll
        for (int l = 0; l < 3; l++) {
            wred[warp][l * 6 + 0] = (double)accS[l];
            wred[warp][l * 6 + 1] = (double)accS2[l];
            wred[warp][l * 6 + 2] = (double)accDX[l];
            wred[warp][l * 6 + 3] = (double)accDY[l];
            wred[warp][l * 6 + 4] = (double)accCX[l];
            wred[warp][l * 6 + 5] = (double)accCY[l];
        }
        wred[warp][18] = dm;
    }
    __syncthreads();
    if (tid < 19) {
        double sum = 0.0;
#pragma unroll
        for (int w = 0; w < 16; w++) sum += wred[w][tid];
        if (tid < 18) {
            int l = tid / 6, k = tid - l * 6;
            g_accs[b * 3 + l][k][s] = sum;
        } else {
            g_mean_partial[b * NSTRIP16 + s] = sum;
        }
    }
}

// ---------------- rank sampling + per-job finalize ----------------
__global__ void __launch_bounds__(512)
k_rank(const float* __restrict__ pred, const float* __restrict__ img1,
       const float* __restrict__ img2) {
    __shared__ int    pref[HH];
    __shared__ int    wsum[16];
    __shared__ int    samp[200];
    __shared__ float  pairbuf[200];
    __shared__ int    cnts[3];
    __shared__ double accs[6];
    __shared__ float  rsum[2];

    const int tid = threadIdx.x, lane = tid & 31, warp = tid >> 5;
    const int job = blockIdx.x;
    const int b = job / 3, li = job - 3 * b;
    const float tgts[3] = {0.077f, 0.227f, 0.348f};
    const float tgtcv = tgts[li];

    if (tid < 200) pairbuf[tid] = 0.0f;  // covers indices 0..199 across two uses below

    // sum per-strip counts / stat accs
    if (tid < 3) {
        int sum = 0;
#pragma unroll
        for (int k = 0; k < NSTRIP32; k++) sum += g_cnts[job][tid][k];
        cnts[tid] = sum;
    }
    if (tid >= 32 && tid < 38) {
        int q = tid - 32;
        double sum = 0.0;
#pragma unroll
        for (int k = 0; k < NSTRIP16; k++) sum += g_accs[job][q][k];
        accs[q] = sum;
    }
    __syncthreads();

    const int n_reg = cnts[0], nE1 = cnts[1], nE2 = cnts[2];
    const uint32_t* C1 = (nE1 < 2) ? g_M[job] : g_E1[job];
    const int       n1 = (nE1 < 2) ? n_reg : nE1;
    const int       n2 = (nE2 < 3) ? n1 : nE2;
    const float* P = pred + (size_t)b * HWSZ;

    // row popcount + two-level warp scan (inclusive)
    int rowc;
    {
        int base = tid * WPR, c = 0;
#pragma unroll
        for (int k = 0; k < WPR; k++) c += __popc(C1[base + k]);
        rowc = c;
    }
    int incl = rowc;
#pragma unroll
    for (int o = 1; o < 32; o <<= 1) {
        int n = __shfl_up_sync(0xffffffffu, incl, o);
        if (lane >= o) incl += n;
    }
    if (lane == 31) wsum[warp] = incl;
    __syncthreads();
    if (warp == 0 && lane < 16) {
        int v = wsum[lane];
        int in2 = v;
#pragma unroll
        for (int o = 1; o < 16; o <<= 1) {
            int n = __shfl_up_sync(0x0000ffffu, in2, o);
            if (lane >= o) in2 += n;
        }
        wsum[lane] = in2 - v;  // exclusive
    }
    __syncthreads();
    pref[tid] = incl + wsum[warp];
    __syncthreads();

    // threefry sampling (JAX key path)
    if (n1 >= 1 && tid < 200) {
        uint32_t o0a, o1a, o0b, o1b, ka, kb;
        int i0, i1; bool first;
        if (job < 24) { i0 = 2 * job;      i1 = 2 * job + 1;  first = true;  }
        else          { i0 = 2 * job - 48; i1 = 2 * job - 47; first = false; }
        threefry(0u, 42u, (uint32_t)i0, (uint32_t)(48 + i0), o0a, o1a);
        threefry(0u, 42u, (uint32_t)i1, (uint32_t)(48 + i1), o0b, o1b);
        ka = first ? o0a : o1a;  kb = first ? o0b : o1b;
        uint32_t p00, p01, p10, p11;
        threefry(ka, kb, 0u, 2u, p00, p01);
        threefry(ka, kb, 1u, 3u, p10, p11);
        uint32_t qk0, qk1;
        if (tid < 100) { qk0 = p00; qk1 = p10; }
        else           { qk0 = p01; qk1 = p11; }
        int q = (tid < 100) ? tid : tid - 100;
        uint32_t b0, b1, bits;
        if (q < 50) { threefry(qk0, qk1, (uint32_t)q,        (uint32_t)(50 + q), b0, b1); bits = b0; }
        else        { threefry(qk0, qk1, (uint32_t)(q - 50), (uint32_t)q,        b0, b1); bits = b1; }
        float u = __uint_as_float((bits >> 9) | 0x3f800000u) - 1.0f;
        float r = 1.0f - u;
        int m = (int)ceilf((float)n1 * r);
        m = min(max(m, 1), n1);
        int lo = 0, hi = HH - 1;
        while (lo < hi) { int mid = (lo + hi) >> 1; if (pref[mid] >= m) hi = mid; else lo = mid + 1; }
        int row = lo;
        int rem = m - (row ? pref[row - 1] : 0);
        int base = row * WPR, col = 0;
        for (int kw = 0; kw < WPR; kw++) {
            uint32_t wv = C1[base + kw];
            int pc = __popc(wv);
            if (rem <= pc) {
                for (int z = 1; z < rem; z++) wv &= wv - 1;
                col = (kw << 5) + (__ffs(wv) - 1);
                break;
            }
            rem -= pc;
        }
        samp[tid] = row * WW + col;
    }
    __syncthreads();

    if (n1 >= 1 && tid < 100) {
        const float* T1 = img1 + (size_t)b * HWSZ;
        const float* T2 = img2 + (size_t)b * HWSZ;
        int ia = samp[tid], jb = samp[100 + tid];
        float xi = 0.5f * (1.0f - T1[ia]) + 0.5f * T2[ia];
        float xj = 0.5f * (1.0f - T1[jb]) + 0.5f * T2[jb];
        float d = xi - xj;
        float sg = (d > 0.0f) ? 1.0f : ((d < 0.0f) ? -1.0f : 0.0f);
        float pv = (ia != jb && sg != 0.0f) ? 1.0f : 0.0f;
        float hinge = fmaxf(0.0f, -(P[ia] - P[jb]) * sg);
        pairbuf[tid] = hinge * pv;
        pairbuf[100 + tid] = pv;
    }
    __syncthreads();

    // warp-reduced pair sums
    if (warp == 0) {
        float h = 0.0f, p = 0.0f;
        for (int i = lane; i < 100; i += 32) { h += pairbuf[i]; p += pairbuf[100 + i]; }
#pragma unroll
        for (int o = 16; o; o >>= 1) {
            h += __shfl_down_sync(0xffffffffu, h, o);
            p += __shfl_down_sync(0xffffffffu, p, o);
        }
        if (lane == 0) { rsum[0] = h; rsum[1] = p; }
    }
    __syncthreads();

    if (tid == 0) {
        double S = accs[0], S2 = accs[1], SDX = accs[2], SDY = accs[3],
               CX = accs[4], CY = accs[5];
        double n2s = (n2 > 1) ? (double)n2 : 1.0;
        double mu = S / n2s;
        double var = S2 / n2s - mu * mu;
        if (var < 0.0) var = 0.0;
        float cv = (float)(sqrt(var) / (fabs(mu) + 1e-6));
        float sv = fabsf(cv - tgtcv);
        float svd = (n_reg >= 3 && n2 >= 3) ? 1.0f : 0.0f;

        double mean_x = SDX / ((CX > 1.0) ? CX : 1.0);
        double mean_y = SDY / ((CY > 1.0) ? CY : 1.0);
        float hx = (CX > 0.0) ? 1.0f : 0.0f;
        float hy = (CY > 0.0) ? 1.0f : 0.0f;
        float npres = hx + hy;
        float mval = (float)((mean_x * hx + mean_y * hy) / ((npres > 1.0f) ? npres : 1.0f));
        float mvd = (n_reg >= 3 && n2 >= 3 && npres > 0.0f) ? 1.0f : 0.0f;

        float hs = (n1 >= 1) ? rsum[0] : 0.0f;
        float npv = (n1 >= 1) ? rsum[1] : 0.0f;
        float rv = hs / fmaxf(npv, 1.0f);
        float rvd = (n_reg >= 2 && n1 >= 2 && npv > 0.0f) ? 1.0f : 0.0f;

        float* o = g_job_out + job * 6;
        o[0] = sv;   o[1] = svd;
        o[2] = rv;   o[3] = rvd;
        o[4] = mval; o[5] = mvd;
    }
}

// ---------------- finalize ----------------
__global__ void k_final(float* __restrict__ out) {
    __shared__ double sh[256];
    int tid = threadIdx.x;
    double s = 0.0;
    for (int i = tid; i < NSTRIP16 * BB; i += 256) s += g_mean_partial[i];
    sh[tid] = s;
    __syncthreads();
    for (int o = 128; o > 0; o >>= 1) {
        if (tid < o) sh[tid] += sh[tid + o];
        __syncthreads();
    }
    if (tid == 0) {
        double lmean = sh[0] / (double)(BB * HWSZ);
        double ss = 0, sc = 0, rs = 0, rc = 0, ms = 0, mc = 0;
        for (int j = 0; j < NJOB; j++) {
            const float* o = g_job_out + j * 6;
            ss += (double)o[0] * o[1]; sc += o[1];
            rs += (double)o[2] * o[3]; rc += o[3];
            ms += (double)o[4] * o[5]; mc += o[5];
        }
        double lstd    = (sc > 0.0) ? ss / sc : 0.0;
        double lrank   = (rc > 0.0) ? rs / rc : 0.0;
        double lsmooth = (mc > 0.0) ? ms / mc : 0.0;
        double loss = (0.5 * lmean + 0.5 * lstd) + lrank + lsmooth;
        out[0] = (float)loss;
    }
}

extern "C" void kernel_launch(void* const* d_in, const int* in_sizes, int n_in,
                              void* d_out, int out_size) {
    const float* pred   = (const float*)d_in[0];
    const float* target = (const float*)d_in[1];
    const int*   lab14  = (const int*)d_in[2];
    const float* img1   = (const float*)d_in[3];
    const float* img2   = (const float*)d_in[4];

    k_mask<<<dim3(NSTRIP32, BB), 512>>>(lab14);
    k_stats<<<dim3(NSTRIP16, BB), 512>>>(pred, target);
    k_rank<<<NJOB, 512>>>(pred, img1, img2);
    k_final<<<1, 256>>>((float*)d_out);
}

// round 12
// speedup vs baseline: 10.6492x; 1.3055x over previous
#include <cuda_runtime.h>
#include <cstdint>

#define HH 512
#define WW 512
#define HWSZ (HH*WW)
#define BB 16
#define NJOB 48
#define NWORDS 8192   /* 512 rows * 16 words */
#define WPR 16
#define NSTRIP16 32   /* k_stats strips (16 rows) */
#define NSTRIP32 16   /* k_mask strips (32 rows) */

__device__ uint32_t g_M [NJOB][NWORDS];
__device__ uint32_t g_E1[NJOB][NWORDS];
__device__ uint32_t g_E2[NJOB][NWORDS];
__device__ int      g_cnts[NJOB][3][NSTRIP32];   // per-strip counts (no atomics)
__device__ double   g_accs[NJOB][6][NSTRIP16];   // per-strip stat sums (no atomics)
__device__ double   g_mean_partial[NSTRIP16 * BB];
__device__ float    g_job_out[NJOB * 6];

__device__ __forceinline__ uint32_t rotl32(uint32_t x, int r) {
    return (x << r) | (x >> (32 - r));
}

// JAX threefry2x32 (20 rounds)
__device__ __forceinline__ void threefry(uint32_t k0, uint32_t k1,
                                         uint32_t x0, uint32_t x1,
                                         uint32_t &o0, uint32_t &o1) {
    uint32_t k2 = k0 ^ k1 ^ 0x1BD11BDAu;
    uint32_t a = x0 + k0, b = x1 + k1;
#define RND(r) { a += b; b = rotl32(b, r); b ^= a; }
    RND(13) RND(15) RND(26) RND(6)  a += k1; b += k2 + 1u;
    RND(17) RND(29) RND(16) RND(24) a += k2; b += k0 + 2u;
    RND(13) RND(15) RND(26) RND(6)  a += k0; b += k1 + 3u;
    RND(17) RND(29) RND(16) RND(24) a += k1; b += k2 + 4u;
    RND(13) RND(15) RND(26) RND(6)  a += k2; b += k0 + 5u;
#undef RND
    o0 = a; o1 = b;
}

// ---------------- masks + erosions, 3 labels per sweep ----------------
__global__ void __launch_bounds__(512)
k_mask(const int* __restrict__ lab14) {
    __shared__ uint32_t Msm[3][576];
    __shared__ uint32_t Tb[3][576];
    __shared__ uint32_t E1s[3][576];
    __shared__ int      wred[16][9];

    const int tid = threadIdx.x, lane = tid & 31, warp = tid >> 5;
    const int s = blockIdx.x, b = blockIdx.y;
    const int r0 = s * 32;
    const int* lab = lab14 + (size_t)b * HWSZ;

    // build 3 masks from one lab pass (out-of-range rows = all ones: inf-pad)
    for (int lw = warp; lw < 576; lw += 16) {
        int lr = lw >> 4, wc = lw & 15;
        int gr = r0 - 2 + lr;
        bool b5 = true, b8 = true, b13 = true;
        if (gr >= 0 && gr < HH) {
            int v = lab[gr * WW + (wc << 5) + lane];
            b5 = (v == 5); b8 = (v == 8); b13 = (v == 13);
        }
        uint32_t m5  = __ballot_sync(0xffffffffu, b5);
        uint32_t m8  = __ballot_sync(0xffffffffu, b8);
        uint32_t m13 = __ballot_sync(0xffffffffu, b13);
        if (lane == 0) { Msm[0][lw] = m5; Msm[1][lw] = m8; Msm[2][lw] = m13; }
    }
    __syncthreads();

    // horizontal erosion, all 3 labels
    for (int lw = tid; lw < 576; lw += 512) {
        int wc = lw & 15;
#pragma unroll
        for (int l = 0; l < 3; l++) {
            uint32_t m = Msm[l][lw];
            uint32_t lb = (m << 1) | (wc ? (Msm[l][lw - 1] >> 31) : 1u);
            uint32_t rb = (m >> 1) | ((wc < 15) ? (Msm[l][lw + 1] << 31) : 0x80000000u);
            Tb[l][lw] = m & lb & rb;
        }
    }
    __syncthreads();
    // vertical -> E1 (out-of-range rows = all ones)
    for (int lw = tid; lw < 576; lw += 512) {
        int lr = lw >> 4;
        int gr = r0 - 2 + lr;
#pragma unroll
        for (int l = 0; l < 3; l++) {
            uint32_t v;
            if (gr < 0 || gr >= HH)       v = 0xffffffffu;
            else if (lr >= 1 && lr <= 34) v = Tb[l][lw] & Tb[l][lw - 16] & Tb[l][lw + 16];
            else                          v = 0u;
            E1s[l][lw] = v;
        }
    }
    __syncthreads();
    // horizontal on E1 -> Tb (reuse)
    for (int lw = tid; lw < 576; lw += 512) {
        int wc = lw & 15;
#pragma unroll
        for (int l = 0; l < 3; l++) {
            uint32_t m = E1s[l][lw];
            uint32_t lb = (m << 1) | (wc ? (E1s[l][lw - 1] >> 31) : 1u);
            uint32_t rb = (m >> 1) | ((wc < 15) ? (E1s[l][lw + 1] << 31) : 0x80000000u);
            Tb[l][lw] = m & lb & rb;
        }
    }
    __syncthreads();
    // vertical -> E2, write out + count
    int cnt[9] = {0,0,0,0,0,0,0,0,0};
    for (int lw = tid; lw < 576; lw += 512) {
        int lr = lw >> 4;
        if (lr >= 2 && lr <= 33) {
            int gw = (r0 + lr - 2) * WPR + (lw & 15);
#pragma unroll
            for (int l = 0; l < 3; l++) {
                uint32_t e2 = Tb[l][lw] & Tb[l][lw - 16] & Tb[l][lw + 16];
                uint32_t m = Msm[l][lw], e1 = E1s[l][lw];
                int job = b * 3 + l;
                g_M[job][gw] = m; g_E1[job][gw] = e1; g_E2[job][gw] = e2;
                cnt[l * 3 + 0] += __popc(m);
                cnt[l * 3 + 1] += __popc(e1);
                cnt[l * 3 + 2] += __popc(e2);
            }
        }
    }
#pragma unroll
    for (int k = 0; k < 9; k++)
#pragma unroll
        for (int o = 16; o; o >>= 1)
            cnt[k] += __shfl_down_sync(0xffffffffu, cnt[k], o);
    if (lane == 0)
#pragma unroll
        for (int k = 0; k < 9; k++) wred[warp][k] = cnt[k];
    __syncthreads();
    if (tid < 9) {
        int sum = 0;
#pragma unroll
        for (int w = 0; w < 16; w++) sum += wred[w][tid];
        int l = tid / 3, c = tid - l * 3;
        g_cnts[b * 3 + l][c][s] = sum;
    }
}

// ---------------- dense stats + smooth + fused mean|pred-target| ----------------
#define SROWS 16
#define MSKW ((SROWS + 1) * WPR)   /* 272 words per label */
__global__ void __launch_bounds__(512)
k_stats(const float* __restrict__ pred, const float* __restrict__ target) {
    __shared__ float    sp[SROWS + 1][WW];   // 17 rows of pred
    __shared__ uint32_t msk[3][MSKW];        // C2 bitmask strip + down halo
    __shared__ double   wred[16][19];
    __shared__ int      sel[3];              // 0=M, 1=E1, 2=E2

    const int tid = threadIdx.x, lane = tid & 31, warp = tid >> 5;
    const int s = blockIdx.x, b = blockIdx.y;
    const int r0 = s * SROWS;
    const float* P = pred   + (size_t)b * HWSZ;
    const float* T = target + (size_t)b * HWSZ;

    // select C2 source per label (sum per-strip counts)
    if (tid < 3) {
        int job = b * 3 + tid;
        int n1c = 0, n2c = 0;
#pragma unroll
        for (int k = 0; k < NSTRIP32; k++) {
            n1c += g_cnts[job][1][k];
            n2c += g_cnts[job][2][k];
        }
        sel[tid] = (n2c >= 3) ? 2 : ((n1c >= 2) ? 1 : 0);
    }

    // stage pred rows + accumulate mean|diff| (17 coalesced rows; mean over 16)
    float amean = 0.0f;
#pragma unroll
    for (int lr = 0; lr <= SROWS; lr++) {
        int gr = r0 + lr;
        float v = (gr < HH) ? P[gr * WW + tid] : 0.0f;
        sp[lr][tid] = v;
        if (lr < SROWS) amean += fabsf(v - T[gr * WW + tid]);
    }
    __syncthreads();

    // stage C2 mask words for 3 labels
    for (int i = tid; i < 3 * MSKW; i += 512) {
        int l = i / MSKW;
        int rem = i - l * MSKW;
        int lr = rem / WPR, wc = rem - lr * WPR;
        int job = b * 3 + l;
        int sl = sel[l];
        const uint32_t* C2 = (sl == 2) ? g_E2[job] : ((sl == 1) ? g_E1[job] : g_M[job]);
        int gr = r0 + lr;
        msk[l][rem] = (gr < HH) ? C2[gr * WPR + wc] : 0u;
    }
    __syncthreads();

    float accS[3]  = {0.f, 0.f, 0.f}, accS2[3] = {0.f, 0.f, 0.f};
    float accDX[3] = {0.f, 0.f, 0.f}, accDY[3] = {0.f, 0.f, 0.f};
    int   accCX[3] = {0, 0, 0},       accCY[3] = {0, 0, 0};

    const int wi  = tid >> 5;
    const int c1  = tid + 1;
    const int wi1 = c1 >> 5, sh1 = c1 & 31;
    const bool hasR = (tid < WW - 1);

#pragma unroll
    for (int lr = 0; lr < SROWS; lr++) {
        float v  = sp[lr][tid];
        float vr = hasR ? sp[lr][tid + 1] : 0.0f;
        float vd = sp[lr + 1][tid];
        float adx = fabsf(vr - v);
        float ady = fabsf(vd - v);
#pragma unroll
        for (int l = 0; l < 3; l++) {
            uint32_t w0 = msk[l][lr * WPR + wi];
            uint32_t in = (w0 >> lane) & 1u;
            if (in) {
                accS[l]  += v;
                accS2[l] += v * v;
                uint32_t rb = hasR ? ((msk[l][lr * WPR + wi1] >> sh1) & 1u) : 0u;
                uint32_t db = (msk[l][(lr + 1) * WPR + wi] >> lane) & 1u;
                if (rb) { accDX[l] += adx; accCX[l]++; }
                if (db) { accDY[l] += ady; accCY[l]++; }
            }
        }
    }

    // warp reduce 18 stat values + mean
#pragma unroll
    for (int l = 0; l < 3; l++) {
#pragma unroll
        for (int o = 16; o; o >>= 1) {
            accS[l]  += __shfl_down_sync(0xffffffffu, accS[l],  o);
            accS2[l] += __shfl_down_sync(0xffffffffu, accS2[l], o);
            accDX[l] += __shfl_down_sync(0xffffffffu, accDX[l], o);
            accDY[l] += __shfl_down_sync(0xffffffffu, accDY[l], o);
            accCX[l] += __shfl_down_sync(0xffffffffu, accCX[l], o);
            accCY[l] += __shfl_down_sync(0xffffffffu, accCY[l], o);
        }
    }
    double dm = (double)amean;
    for (int o = 16; o; o >>= 1) dm += __shfl_down_sync(0xffffffffu, dm, o);

    if (lane == 0) {
#pragma unroll
        for (int l = 0; l < 3; l++) {
            wred[warp][l * 6 + 0] = (double)accS[l];
            wred[warp][l * 6 + 1] = (double)accS2[l];
            wred[warp][l * 6 + 2] = (double)accDX[l];
            wred[warp][l * 6 + 3] = (double)accDY[l];
            wred[warp][l * 6 + 4] = (double)accCX[l];
            wred[warp][l * 6 + 5] = (double)accCY[l];
        }
        wred[warp][18] = dm;
    }
    __syncthreads();
    if (tid < 19) {
        double sum = 0.0;
#pragma unroll
        for (int w = 0; w < 16; w++) sum += wred[w][tid];
        if (tid < 18) {
            int l = tid / 6, k = tid - l * 6;
            g_accs[b * 3 + l][k][s] = sum;
        } else {
            g_mean_partial[b * NSTRIP16 + s] = sum;
        }
    }
}

// ---------------- rank sampling + per-job finalize ----------------
__global__ void __launch_bounds__(512)
k_rank(const float* __restrict__ pred, const float* __restrict__ img1,
       const float* __restrict__ img2) {
    __shared__ int    pref[HH];
    __shared__ int    wsum[16];
    __shared__ int    samp[200];
    __shared__ float  pairbuf[200];
    __shared__ int    cnts[3];
    __shared__ double accs[6];
    __shared__ float  rsum[2];

    const int tid = threadIdx.x, lane = tid & 31, warp = tid >> 5;
    const int job = blockIdx.x;
    const int b = job / 3, li = job - 3 * b;
    const float tgts[3] = {0.077f, 0.227f, 0.348f};
    const float tgtcv = tgts[li];

    if (tid < 200) pairbuf[tid] = 0.0f;

    // sum per-strip counts / stat accs
    if (tid < 3) {
        int sum = 0;
#pragma unroll
        for (int k = 0; k < NSTRIP32; k++) sum += g_cnts[job][tid][k];
        cnts[tid] = sum;
    }
    if (tid >= 32 && tid < 38) {
        int q = tid - 32;
        double sum = 0.0;
#pragma unroll
        for (int k = 0; k < NSTRIP16; k++) sum += g_accs[job][q][k];
        accs[q] = sum;
    }
    __syncthreads();

    const int n_reg = cnts[0], nE1 = cnts[1], nE2 = cnts[2];
    const uint32_t* C1 = (nE1 < 2) ? g_M[job] : g_E1[job];
    const int       n1 = (nE1 < 2) ? n_reg : nE1;
    const int       n2 = (nE2 < 3) ? n1 : nE2;
    const float* P = pred + (size_t)b * HWSZ;

    // row popcount + two-level warp scan (inclusive)
    int rowc;
    {
        int base = tid * WPR, c = 0;
#pragma unroll
        for (int k = 0; k < WPR; k++) c += __popc(C1[base + k]);
        rowc = c;
    }
    int incl = rowc;
#pragma unroll
    for (int o = 1; o < 32; o <<= 1) {
        int n = __shfl_up_sync(0xffffffffu, incl, o);
        if (lane >= o) incl += n;
    }
    if (lane == 31) wsum[warp] = incl;
    __syncthreads();
    if (warp == 0 && lane < 16) {
        int v = wsum[lane];
        int in2 = v;
#pragma unroll
        for (int o = 1; o < 16; o <<= 1) {
            int n = __shfl_up_sync(0x0000ffffu, in2, o);
            if (lane >= o) in2 += n;
        }
        wsum[lane] = in2 - v;  // exclusive
    }
    __syncthreads();
    pref[tid] = incl + wsum[warp];
    __syncthreads();

    // threefry sampling (JAX key path)
    if (n1 >= 1 && tid < 200) {
        uint32_t o0a, o1a, o0b, o1b, ka, kb;
        int i0, i1; bool first;
        if (job < 24) { i0 = 2 * job;      i1 = 2 * job + 1;  first = true;  }
        else          { i0 = 2 * job - 48; i1 = 2 * job - 47; first = false; }
        threefry(0u, 42u, (uint32_t)i0, (uint32_t)(48 + i0), o0a, o1a);
        threefry(0u, 42u, (uint32_t)i1, (uint32_t)(48 + i1), o0b, o1b);
        ka = first ? o0a : o1a;  kb = first ? o0b : o1b;
        uint32_t p00, p01, p10, p11;
        threefry(ka, kb, 0u, 2u, p00, p01);
        threefry(ka, kb, 1u, 3u, p10, p11);
        uint32_t qk0, qk1;
        if (tid < 100) { qk0 = p00; qk1 = p10; }
        else           { qk0 = p01; qk1 = p11; }
        int q = (tid < 100) ? tid : tid - 100;
        uint32_t b0, b1, bits;
        if (q < 50) { threefry(qk0, qk1, (uint32_t)q,        (uint32_t)(50 + q), b0, b1); bits = b0; }
        else        { threefry(qk0, qk1, (uint32_t)(q - 50), (uint32_t)q,        b0, b1); bits = b1; }
        float u = __uint_as_float((bits >> 9) | 0x3f800000u) - 1.0f;
        float r = 1.0f - u;
        int m = (int)ceilf((float)n1 * r);
        m = min(max(m, 1), n1);
        int lo = 0, hi = HH - 1;
        while (lo < hi) { int mid = (lo + hi) >> 1; if (pref[mid] >= m) hi = mid; else lo = mid + 1; }
        int row = lo;
        int rem = m - (row ? pref[row - 1] : 0);
        int base = row * WPR, col = 0;
        for (int kw = 0; kw < WPR; kw++) {
            uint32_t wv = C1[base + kw];
            int pc = __popc(wv);
            if (rem <= pc) {
                for (int z = 1; z < rem; z++) wv &= wv - 1;
                col = (kw << 5) + (__ffs(wv) - 1);
                break;
            }
            rem -= pc;
        }
        samp[tid] = row * WW + col;
    }
    __syncthreads();

    if (n1 >= 1 && tid < 100) {
        const float* T1 = img1 + (size_t)b * HWSZ;
        const float* T2 = img2 + (size_t)b * HWSZ;
        int ia = samp[tid], jb = samp[100 + tid];
        float xi = 0.5f * (1.0f - T1[ia]) + 0.5f * T2[ia];
        float xj = 0.5f * (1.0f - T1[jb]) + 0.5f * T2[jb];
        float d = xi - xj;
        float sg = (d > 0.0f) ? 1.0f : ((d < 0.0f) ? -1.0f : 0.0f);
        float pv = (ia != jb && sg != 0.0f) ? 1.0f : 0.0f;
        float hinge = fmaxf(0.0f, -(P[ia] - P[jb]) * sg);
        pairbuf[tid] = hinge * pv;
        pairbuf[100 + tid] = pv;
    }
    __syncthreads();

    // warp-reduced pair sums
    if (warp == 0) {
        float h = 0.0f, p = 0.0f;
        for (int i = lane; i < 100; i += 32) { h += pairbuf[i]; p += pairbuf[100 + i]; }
#pragma unroll
        for (int o = 16; o; o >>= 1) {
            h += __shfl_down_sync(0xffffffffu, h, o);
            p += __shfl_down_sync(0xffffffffu, p, o);
        }
        if (lane == 0) { rsum[0] = h; rsum[1] = p; }
    }
    __syncthreads();

    if (tid == 0) {
        double S = accs[0], S2 = accs[1], SDX = accs[2], SDY = accs[3],
               CX = accs[4], CY = accs[5];
        double n2s = (n2 > 1) ? (double)n2 : 1.0;
        double mu = S / n2s;
        double var = S2 / n2s - mu * mu;
        if (var < 0.0) var = 0.0;
        float cv = (float)(sqrt(var) / (fabs(mu) + 1e-6));
        float sv = fabsf(cv - tgtcv);
        float svd = (n_reg >= 3 && n2 >= 3) ? 1.0f : 0.0f;

        double mean_x = SDX / ((CX > 1.0) ? CX : 1.0);
        double mean_y = SDY / ((CY > 1.0) ? CY : 1.0);
        float hx = (CX > 0.0) ? 1.0f : 0.0f;
        float hy = (CY > 0.0) ? 1.0f : 0.0f;
        float npres = hx + hy;
        float mval = (float)((mean_x * hx + mean_y * hy) / ((npres > 1.0f) ? npres : 1.0f));
        float mvd = (n_reg >= 3 && n2 >= 3 && npres > 0.0f) ? 1.0f : 0.0f;

        float hs = (n1 >= 1) ? rsum[0] : 0.0f;
        float npv = (n1 >= 1) ? rsum[1] : 0.0f;
        float rv = hs / fmaxf(npv, 1.0f);
        float rvd = (n_reg >= 2 && n1 >= 2 && npv > 0.0f) ? 1.0f : 0.0f;

        float* o = g_job_out + job * 6;
        o[0] = sv;   o[1] = svd;
        o[2] = rv;   o[3] = rvd;
        o[4] = mval; o[5] = mvd;
    }
}

// ---------------- finalize (parallel job combine) ----------------
__global__ void __launch_bounds__(512) k_final(float* __restrict__ out) {
    __shared__ double sh[512];
    __shared__ double jred[2][6];
    const int tid = threadIdx.x, lane = tid & 31, warp = tid >> 5;

    // mean partials: 512 entries, one per thread
    sh[tid] = g_mean_partial[tid];
    __syncthreads();
    for (int o = 256; o > 0; o >>= 1) {
        if (tid < o) sh[tid] += sh[tid + o];
        __syncthreads();
    }

    // per-job masked sums: 48 threads load 6 floats each, reduce over 2 warps
    double ss = 0, sc = 0, rs = 0, rc = 0, ms = 0, mc = 0;
    if (tid < NJOB) {
        const float* o = g_job_out + tid * 6;
        float v0 = o[0], v1 = o[1], v2 = o[2], v3 = o[3], v4 = o[4], v5 = o[5];
        ss = (double)v0 * v1; sc = v1;
        rs = (double)v2 * v3; rc = v3;
        ms = (double)v4 * v5; mc = v5;
    }
    if (warp < 2) {
#pragma unroll
        for (int o = 16; o; o >>= 1) {
            ss += __shfl_down_sync(0xffffffffu, ss, o);
            sc += __shfl_down_sync(0xffffffffu, sc, o);
            rs += __shfl_down_sync(0xffffffffu, rs, o);
            rc += __shfl_down_sync(0xffffffffu, rc, o);
            ms += __shfl_down_sync(0xffffffffu, ms, o);
            mc += __shfl_down_sync(0xffffffffu, mc, o);
        }
        if (lane == 0) {
            jred[warp][0] = ss; jred[warp][1] = sc;
            jred[warp][2] = rs; jred[warp][3] = rc;
            jred[warp][4] = ms; jred[warp][5] = mc;
        }
    }
    __syncthreads();

    if (tid == 0) {
        double lmean = sh[0] / (double)(BB * HWSZ);
        double SS = jred[0][0] + jred[1][0], SC = jred[0][1] + jred[1][1];
        double RS = jred[0][2] + jred[1][2], RC = jred[0][3] + jred[1][3];
        double MS = jred[0][4] + jred[1][4], MC = jred[0][5] + jred[1][5];
        double lstd    = (SC > 0.0) ? SS / SC : 0.0;
        double lrank   = (RC > 0.0) ? RS / RC : 0.0;
        double lsmooth = (MC > 0.0) ? MS / MC : 0.0;
        double loss = (0.5 * lmean + 0.5 * lstd) + lrank + lsmooth;
        out[0] = (float)loss;
    }
}

extern "C" void kernel_launch(void* const* d_in, const int* in_sizes, int n_in,
                              void* d_out, int out_size) {
    const float* pred   = (const float*)d_in[0];
    const float* target = (const float*)d_in[1];
    const int*   lab14  = (const int*)d_in[2];
    const float* img1   = (const float*)d_in[3];
    const float* img2   = (const float*)d_in[4];

    k_mask<<<dim3(NSTRIP32, BB), 512>>>(lab14);
    k_stats<<<dim3(NSTRIP16, BB), 512>>>(pred, target);
    k_rank<<<NJOB, 512>>>(pred, img1, img2);
    k_final<<<1, 512>>>((float*)d_out);
}